// round 2
// baseline (speedup 1.0000x reference)
#include <cuda_runtime.h>

#define BATCH   64
#define CH      36
#define NCLS    32
#define ANCH    8400
#define NT      512          // threads per CTA (power of two; anchor = slot*NT + tid)
#define NT_LOG2 9
#define PER     17           // ceil(8400/512)
#define APAD    (NT*PER)     // 8704
#define MAXDET  100
#define CONF_T  0.25f
#define IOU_T   0.45f

// order-preserving float->u32 map (monotone for all finite floats)
static __device__ __forceinline__ unsigned mapf(float f) {
    unsigned u = __float_as_uint(f);
    return (u & 0x80000000u) ? ~u : (u | 0x80000000u);
}
static __device__ __forceinline__ float unmapf(unsigned u) {
    return __uint_as_float((u & 0x80000000u) ? (u ^ 0x80000000u) : ~u);
}

// SMEM: boxes(float4)[APAD] | area[APAD] | class[APAD] | partials u64[2][16]
#define SMEM_BYTES (APAD*16 + APAD*4 + APAD*4 + 2*16*8)

__global__ __launch_bounds__(NT, 1)
void yolo_nms_kernel(const float* __restrict__ in, float* __restrict__ out)
{
    extern __shared__ char smem_raw[];
    float4* sbox = (float4*)smem_raw;
    float*  sarea = (float*)(smem_raw + (size_t)APAD * sizeof(float4));
    float*  scls  = sarea + APAD;
    unsigned long long* spart = (unsigned long long*)(scls + APAD);

    const int tid  = threadIdx.x;
    const int b    = blockIdx.x;
    const int wid  = tid >> 5;
    const int lane = tid & 31;
    const float* base = in + (size_t)b * CH * ANCH;

    float* boxes_out = out + (size_t)b * MAXDET * 4;
    float* cls_out   = out + (size_t)BATCH * MAXDET * 4 + (size_t)b * MAXDET;
    float* sco_out   = out + (size_t)BATCH * MAXDET * 5 + (size_t)b * MAXDET;
    float* nd_out    = out + (size_t)BATCH * MAXDET * 6 + b;

    // ---------------- Phase 1: decode ----------------
    float sc[PER];
    unsigned mask = 0;   // bit s set => slot s active (score > 0, not suppressed)

    #pragma unroll
    for (int s = 0; s < PER; s++) {
        int a = s * NT + tid;
        float4 bx = make_float4(0.f, 0.f, 0.f, 0.f);
        float cl = 0.f, ms = -2.0f, area = 0.f;
        if (a < ANCH) {
            float xc = base[a];
            float yc = base[ANCH + a];
            float w  = base[2 * ANCH + a];
            float h  = base[3 * ANCH + a];
            float best = base[4 * ANCH + a];
            int bc = 0;
            #pragma unroll
            for (int c = 1; c < NCLS; c++) {
                float v = base[(4 + c) * ANCH + a];
                if (v > best) { best = v; bc = c; }   // first-max, matches jnp.argmax
            }
            cl = (float)bc;
            // corner = [clip(yc-h/2), clip(xc-w/2), clip(yc+h/2), clip(xc+w/2)]
            float y1 = fminf(fmaxf(yc - 0.5f * h, 0.f), 1.f);
            float x1 = fminf(fmaxf(xc - 0.5f * w, 0.f), 1.f);
            float y2 = fminf(fmaxf(yc + 0.5f * h, 0.f), 1.f);
            float x2 = fminf(fmaxf(xc + 0.5f * w, 0.f), 1.f);
            bx = make_float4(y1, x1, y2, x2);
            area = __fmul_rn(__fsub_rn(y2, y1), __fsub_rn(x2, x1));
            ms = (best >= CONF_T) ? best : -1.0f;
            if (ms > 0.0f) mask |= (1u << s);
        }
        sc[s]   = ms;
        sbox[a] = bx;
        sarea[a] = area;
        scls[a] = cl;
    }
    __syncthreads();

    // initial cached local argmax (key = mapped_score<<32 | inverted anchor index)
    unsigned long long local = 0ull;
    #pragma unroll
    for (int s = 0; s < PER; s++) {
        if (mask & (1u << s)) {
            unsigned long long k =
                ((unsigned long long)mapf(sc[s]) << 32) |
                (unsigned)(0x00FFFFFF - (s * NT + tid));
            if (k > local) local = k;
        }
    }

    // ---------------- Phase 2: greedy NMS (100 steps) ----------------
    for (int i = 0; i < MAXDET; i++) {
        // block-wide argmax: warp butterfly -> partials -> redundant final reduce
        unsigned long long k = local;
        #pragma unroll
        for (int off = 16; off >= 1; off >>= 1) {
            unsigned long long o = __shfl_xor_sync(0xFFFFFFFFu, k, off);
            if (o > k) k = o;
        }
        if (lane == 0) spart[(i & 1) * 16 + wid] = k;
        __syncthreads();
        unsigned long long k2 = (lane < 16) ? spart[(i & 1) * 16 + lane] : 0ull;
        #pragma unroll
        for (int off = 16; off >= 1; off >>= 1) {
            unsigned long long o = __shfl_xor_sync(0xFFFFFFFFu, k2, off);
            if (o > k2) k2 = o;
        }

        float wscore = unmapf((unsigned)(k2 >> 32));
        if (!(wscore > 0.0f)) {
            // remaining detections are all zeros; num_det = i
            for (int t = i * 4 + tid; t < MAXDET * 4; t += NT) boxes_out[t] = 0.f;
            for (int t = i + tid; t < MAXDET; t += NT) { cls_out[t] = 0.f; sco_out[t] = 0.f; }
            if (tid == 0) *nd_out = (float)i;
            return;
        }

        int idx = 0x00FFFFFF - (int)(unsigned)(k2 & 0xFFFFFFFFull);
        float4 wb = sbox[idx];
        float  wa = sarea[idx];

        if (tid == 0) {
            boxes_out[i * 4 + 0] = wb.x;
            boxes_out[i * 4 + 1] = wb.y;
            boxes_out[i * 4 + 2] = wb.z;
            boxes_out[i * 4 + 3] = wb.w;
            cls_out[i] = scls[idx];
            sco_out[i] = wscore;
        }

        // suppression: only over still-active slots (sparse bitmask walk)
        unsigned cleared = 0;
        unsigned m = mask;
        while (m) {
            int s = __ffs(m) - 1;
            m &= m - 1;
            int a = s * NT + tid;
            float4 bb = sbox[a];
            float yy1 = fmaxf(wb.x, bb.x);
            float xx1 = fmaxf(wb.y, bb.y);
            float yy2 = fminf(wb.z, bb.z);
            float xx2 = fminf(wb.w, bb.w);
            float dy = fmaxf(__fsub_rn(yy2, yy1), 0.f);
            float dx = fmaxf(__fsub_rn(xx2, xx1), 0.f);
            float inter = __fmul_rn(dy, dx);
            float uni = __fsub_rn(__fadd_rn(wa, sarea[a]), inter);
            if (uni > 0.f && __fdiv_rn(inter, uni) > IOU_T)   // IEEE div: bit-matches ref
                cleared |= (1u << s);
        }
        // winner slot always dies (handles degenerate zero-area self box)
        if ((idx & (NT - 1)) == tid) cleared |= 1u << (idx >> NT_LOG2);

        if (cleared) {
            mask &= ~cleared;
            if (local) {
                unsigned la = 0x00FFFFFFu - (unsigned)(local & 0xFFFFFFFFull);
                int bs = (int)(la >> NT_LOG2);
                if (cleared & (1u << bs)) {      // cached best died -> rescan
                    local = 0ull;
                    #pragma unroll
                    for (int s = 0; s < PER; s++) {
                        if (mask & (1u << s)) {
                            unsigned long long kk =
                                ((unsigned long long)mapf(sc[s]) << 32) |
                                (unsigned)(0x00FFFFFF - (s * NT + tid));
                            if (kk > local) local = kk;
                        }
                    }
                }
            }
        }
    }
    if (tid == 0) *nd_out = (float)MAXDET;
}

extern "C" void kernel_launch(void* const* d_in, const int* in_sizes, int n_in,
                              void* d_out, int out_size)
{
    (void)in_sizes; (void)n_in; (void)out_size;
    const float* in = (const float*)d_in[0];
    float* out = (float*)d_out;
    cudaFuncSetAttribute(yolo_nms_kernel,
                         cudaFuncAttributeMaxDynamicSharedMemorySize, SMEM_BYTES);
    yolo_nms_kernel<<<BATCH, NT, SMEM_BYTES>>>(in, out);
}

// round 3
// speedup vs baseline: 1.9759x; 1.9759x over previous
#include <cuda_runtime.h>

#define BATCH   64
#define CH      36
#define NCLS    32
#define ANCH    8400
#define NT      512          // threads per CTA (power of two; anchor = slot*NT + tid)
#define NT_LOG2 9
#define PER     17           // ceil(8400/512)
#define APAD    (NT*PER)     // 8704
#define MAXDET  100
#define CONF_T  0.25f
#define IOU_T   0.45f

// order-preserving float->u32 map (monotone for all finite floats)
static __device__ __forceinline__ unsigned mapf(float f) {
    unsigned u = __float_as_uint(f);
    return (u & 0x80000000u) ? ~u : (u | 0x80000000u);
}
static __device__ __forceinline__ float unmapf(unsigned u) {
    return __uint_as_float((u & 0x80000000u) ? (u ^ 0x80000000u) : ~u);
}

// SMEM: boxes(float4)[APAD] | area[APAD] | class[APAD] | partials u64[2][16]
#define SMEM_BYTES (APAD*16 + APAD*4 + APAD*4 + 2*16*8)

__global__ __launch_bounds__(NT, 1)
void yolo_nms_kernel(const float* __restrict__ in, float* __restrict__ out)
{
    extern __shared__ char smem_raw[];
    float4* sbox = (float4*)smem_raw;
    float*  sarea = (float*)(smem_raw + (size_t)APAD * sizeof(float4));
    float*  scls  = sarea + APAD;
    unsigned long long* spart = (unsigned long long*)(scls + APAD);

    const int tid  = threadIdx.x;
    const int b    = blockIdx.x;
    const int wid  = tid >> 5;
    const int lane = tid & 31;
    const float* base = in + (size_t)b * CH * ANCH;

    float* boxes_out = out + (size_t)b * MAXDET * 4;
    float* cls_out   = out + (size_t)BATCH * MAXDET * 4 + (size_t)b * MAXDET;
    float* sco_out   = out + (size_t)BATCH * MAXDET * 5 + (size_t)b * MAXDET;
    float* nd_out    = out + (size_t)BATCH * MAXDET * 6 + b;

    // ---------------- Phase 1: decode ----------------
    unsigned msc[PER];   // pre-mapped (order-preserving u32) masked score
    unsigned mask = 0;   // bit s set => slot s active (score > 0, not suppressed)

    #pragma unroll
    for (int s = 0; s < PER; s++) {
        int a = s * NT + tid;
        float4 bx = make_float4(0.f, 0.f, 0.f, 0.f);
        float cl = 0.f, area = 0.f;
        unsigned mm = 0;
        if (a < ANCH) {
            float xc = base[a];
            float yc = base[ANCH + a];
            float w  = base[2 * ANCH + a];
            float h  = base[3 * ANCH + a];
            float best = base[4 * ANCH + a];
            int bc = 0;
            #pragma unroll
            for (int c = 1; c < NCLS; c++) {
                float v = base[(4 + c) * ANCH + a];
                if (v > best) { best = v; bc = c; }   // first-max, matches jnp.argmax
            }
            cl = (float)bc;
            // corner = [clip(yc-h/2), clip(xc-w/2), clip(yc+h/2), clip(xc+w/2)]
            float y1 = fminf(fmaxf(yc - 0.5f * h, 0.f), 1.f);
            float x1 = fminf(fmaxf(xc - 0.5f * w, 0.f), 1.f);
            float y2 = fminf(fmaxf(yc + 0.5f * h, 0.f), 1.f);
            float x2 = fminf(fmaxf(xc + 0.5f * w, 0.f), 1.f);
            bx = make_float4(y1, x1, y2, x2);
            area = __fmul_rn(__fsub_rn(y2, y1), __fsub_rn(x2, x1));
            if (best >= CONF_T) {            // masked score > 0 (uniform data: best>0)
                mm = mapf(best);
                mask |= (1u << s);
            }
        }
        msc[s]  = mm;
        sbox[a] = bx;
        sarea[a] = area;
        scls[a] = cl;
    }
    __syncthreads();

    // initial cached local argmax (key = mapped_score<<32 | inverted anchor index)
    unsigned long long local = 0ull;
    #pragma unroll
    for (int s = 0; s < PER; s++) {
        if (mask & (1u << s)) {
            unsigned long long k =
                ((unsigned long long)msc[s] << 32) |
                (unsigned)(0x00FFFFFF - (s * NT + tid));
            if (k > local) local = k;
        }
    }

    // ---------------- Phase 2: greedy NMS (100 steps) ----------------
    for (int i = 0; i < MAXDET; i++) {
        // block-wide argmax: warp butterfly -> partials -> redundant final reduce
        unsigned long long k = local;
        #pragma unroll
        for (int off = 16; off >= 1; off >>= 1) {
            unsigned long long o = __shfl_xor_sync(0xFFFFFFFFu, k, off);
            if (o > k) k = o;
        }
        if (lane == 0) spart[(i & 1) * 16 + wid] = k;
        __syncthreads();
        unsigned long long k2 = (lane < 16) ? spart[(i & 1) * 16 + lane] : 0ull;
        #pragma unroll
        for (int off = 16; off >= 1; off >>= 1) {
            unsigned long long o = __shfl_xor_sync(0xFFFFFFFFu, k2, off);
            if (o > k2) k2 = o;
        }

        unsigned wkey_hi = (unsigned)(k2 >> 32);
        if (wkey_hi <= 0x80000000u) {        // mapped(score) <= mapped(0)  <=>  score <= 0
            // remaining detections are all zeros; num_det = i
            for (int t = i * 4 + tid; t < MAXDET * 4; t += NT) boxes_out[t] = 0.f;
            for (int t = i + tid; t < MAXDET; t += NT) { cls_out[t] = 0.f; sco_out[t] = 0.f; }
            if (tid == 0) *nd_out = (float)i;
            return;
        }

        int idx = 0x00FFFFFF - (int)(unsigned)(k2 & 0xFFFFFFFFull);
        float4 wb = sbox[idx];
        float  wa = sarea[idx];

        if (tid == 0) {
            boxes_out[i * 4 + 0] = wb.x;
            boxes_out[i * 4 + 1] = wb.y;
            boxes_out[i * 4 + 2] = wb.z;
            boxes_out[i * 4 + 3] = wb.w;
            cls_out[i] = scls[idx];
            sco_out[i] = unmapf(wkey_hi);
        }

        // suppression: only over still-active slots (sparse bitmask walk).
        // Division replaced by guard-banded FMA test; exact __fdiv_rn only in
        // the ~3e-7-wide ambiguity band (provably identical decisions outside it).
        unsigned cleared = 0;
        unsigned m = mask;
        while (m) {
            int s = __ffs(m) - 1;
            m &= m - 1;
            int a = (s << NT_LOG2) + tid;
            float4 bb = sbox[a];
            float yy1 = fmaxf(wb.x, bb.x);
            float xx1 = fmaxf(wb.y, bb.y);
            float yy2 = fminf(wb.z, bb.z);
            float xx2 = fminf(wb.w, bb.w);
            float dy = fmaxf(__fsub_rn(yy2, yy1), 0.f);
            float dx = fmaxf(__fsub_rn(xx2, xx1), 0.f);
            float inter = __fmul_rn(dy, dx);
            float uni = __fsub_rn(__fadd_rn(wa, sarea[a]), inter);
            float t   = __fmaf_rn(-IOU_T, uni, inter);
            float bnd = 3e-7f * uni;
            bool sup;
            if (t > bnd)       sup = true;
            else if (t < -bnd) sup = false;
            else               sup = (uni > 0.f) && (__fdiv_rn(inter, uni) > IOU_T);
            if (sup) cleared |= (1u << s);
        }
        // winner slot always dies (handles degenerate zero-area self box)
        if ((idx & (NT - 1)) == tid) cleared |= 1u << (idx >> NT_LOG2);

        if (cleared) {
            mask &= ~cleared;
            if (local) {
                unsigned la = 0x00FFFFFFu - (unsigned)(local & 0xFFFFFFFFull);
                int bs = (int)(la >> NT_LOG2);
                if (cleared & (1u << bs)) {      // cached best died -> rescan (regs only)
                    local = 0ull;
                    #pragma unroll
                    for (int s = 0; s < PER; s++) {
                        if (mask & (1u << s)) {
                            unsigned long long kk =
                                ((unsigned long long)msc[s] << 32) |
                                (unsigned)(0x00FFFFFF - (s * NT + tid));
                            if (kk > local) local = kk;
                        }
                    }
                }
            }
        }
    }
    if (tid == 0) *nd_out = (float)MAXDET;
}

extern "C" void kernel_launch(void* const* d_in, const int* in_sizes, int n_in,
                              void* d_out, int out_size)
{
    (void)in_sizes; (void)n_in; (void)out_size;
    const float* in = (const float*)d_in[0];
    float* out = (float*)d_out;
    cudaFuncSetAttribute(yolo_nms_kernel,
                         cudaFuncAttributeMaxDynamicSharedMemorySize, SMEM_BYTES);
    yolo_nms_kernel<<<BATCH, NT, SMEM_BYTES>>>(in, out);
}

// round 4
// speedup vs baseline: 2.2616x; 1.1446x over previous
#include <cuda_runtime.h>

#define BATCH   64
#define CH      36
#define NCLS    32
#define ANCH    8400
#define CLU     2
#define ANCHH   (ANCH / CLU)   // 4200 anchors per CTA
#define NT      512
#define NT_LOG2 9
#define PERH    9              // ceil(4200/512)
#define APADH   (NT * PERH)    // 4608
#define MAXDET  100
#define CONF_T  0.25f
#define IOU_T   0.45f

// order-preserving float->u32 map (monotone for all finite floats)
static __device__ __forceinline__ unsigned mapf(float f) {
    unsigned u = __float_as_uint(f);
    return (u & 0x80000000u) ? ~u : (u | 0x80000000u);
}
static __device__ __forceinline__ float unmapf(unsigned u) {
    return __uint_as_float((u & 0x80000000u) ? (u ^ 0x80000000u) : ~u);
}
static __device__ __forceinline__ unsigned smem_u32(const void* p) {
    return (unsigned)__cvta_generic_to_shared(p);
}
static __device__ __forceinline__ unsigned long long pack2f(float lo, float hi) {
    return ((unsigned long long)__float_as_uint(hi) << 32) | __float_as_uint(lo);
}

// SMEM: boxes(float4)[APADH] | area[APADH] | cls[APADH] | spart u64[2][16] | mbox u64[2][4]
#define SMEM_BYTES (APADH*16 + APADH*4 + APADH*4 + 2*16*8 + 2*4*8)

__global__ __launch_bounds__(NT, 1) __cluster_dims__(CLU, 1, 1)
void yolo_nms_kernel(const float* __restrict__ in, float* __restrict__ out)
{
    extern __shared__ char smem_raw[];
    float4* sbox = (float4*)smem_raw;
    float*  sarea = (float*)(smem_raw + (size_t)APADH * sizeof(float4));
    float*  scls  = sarea + APADH;
    unsigned long long* spart = (unsigned long long*)(scls + APADH);
    unsigned long long* mbox  = spart + 32;   // [2][4]: key, box01, box23, (area,cls)

    const int tid   = threadIdx.x;
    const int rank  = (int)(blockIdx.x & (CLU - 1));
    const int b     = (int)(blockIdx.x / CLU);
    const int wid   = tid >> 5;
    const int lane  = tid & 31;
    const int abase = rank * ANCHH;                 // global anchor offset of my half
    const float* base = in + (size_t)b * CH * ANCH;

    float* boxes_out = out + (size_t)b * MAXDET * 4;
    float* cls_out   = out + (size_t)BATCH * MAXDET * 4 + (size_t)b * MAXDET;
    float* sco_out   = out + (size_t)BATCH * MAXDET * 5 + (size_t)b * MAXDET;
    float* nd_out    = out + (size_t)BATCH * MAXDET * 6 + b;

    // peer's mailbox base (DSMEM)
    unsigned my_mbox = smem_u32(mbox);
    unsigned peer_mbox;
    asm("mapa.shared::cluster.u32 %0, %1, %2;"
        : "=r"(peer_mbox) : "r"(my_mbox), "r"(rank ^ 1));

    // ---------------- Phase 1: decode my half ----------------
    unsigned msc[PERH];    // pre-mapped masked score per slot
    unsigned mask = 0;     // bit s set => slot s active

    #pragma unroll
    for (int s = 0; s < PERH; s++) {
        int a = s * NT + tid;            // local index in my half
        int g = abase + a;               // global anchor index
        float4 bx = make_float4(0.f, 0.f, 0.f, 0.f);
        float cl = 0.f, area = 0.f;
        unsigned mm = 0;
        if (a < ANCHH) {
            float xc = base[g];
            float yc = base[ANCH + g];
            float w  = base[2 * ANCH + g];
            float h  = base[3 * ANCH + g];
            float best = base[4 * ANCH + g];
            int bc = 0;
            #pragma unroll
            for (int c = 1; c < NCLS; c++) {
                float v = base[(4 + c) * ANCH + g];
                if (v > best) { best = v; bc = c; }   // first-max == jnp.argmax
            }
            cl = (float)bc;
            float y1 = fminf(fmaxf(yc - 0.5f * h, 0.f), 1.f);
            float x1 = fminf(fmaxf(xc - 0.5f * w, 0.f), 1.f);
            float y2 = fminf(fmaxf(yc + 0.5f * h, 0.f), 1.f);
            float x2 = fminf(fmaxf(xc + 0.5f * w, 0.f), 1.f);
            bx = make_float4(y1, x1, y2, x2);
            area = __fmul_rn(__fsub_rn(y2, y1), __fsub_rn(x2, x1));
            if (best >= CONF_T) { mm = mapf(best); mask |= (1u << s); }
        }
        msc[s]   = mm;
        sbox[a]  = bx;
        sarea[a] = area;
        scls[a]  = cl;
    }
    __syncthreads();

    // cached local argmax (key = mapped_score<<32 | inverted GLOBAL index)
    unsigned long long local = 0ull;
    #pragma unroll
    for (int s = 0; s < PERH; s++) {
        if (mask & (1u << s)) {
            unsigned long long k =
                ((unsigned long long)msc[s] << 32) |
                (unsigned)(0x00FFFFFF - (abase + s * NT + tid));
            if (k > local) local = k;
        }
    }

    // ---------------- Phase 2: greedy NMS (100 steps) ----------------
    for (int i = 0; i < MAXDET; i++) {
        // CTA-local argmax: warp butterfly -> partials -> redundant final reduce
        unsigned long long k = local;
        #pragma unroll
        for (int off = 16; off >= 1; off >>= 1) {
            unsigned long long o = __shfl_xor_sync(0xFFFFFFFFu, k, off);
            if (o > k) k = o;
        }
        if (lane == 0) spart[(i & 1) * 16 + wid] = k;
        __syncthreads();
        unsigned long long k2 = (lane < 16) ? spart[(i & 1) * 16 + lane] : 0ull;
        #pragma unroll
        for (int off = 16; off >= 1; off >>= 1) {
            unsigned long long o = __shfl_xor_sync(0xFFFFFFFFu, k2, off);
            if (o > k2) k2 = o;
        }

        // publish my CTA winner {key, box, area+cls} to the PEER's mailbox
        if (tid == 0) {
            unsigned long long p1 = 0, p2 = 0, p3 = 0;
            if ((unsigned)(k2 >> 32) > 0x80000000u) {
                int g  = 0x00FFFFFF - (int)(unsigned)(k2 & 0xFFFFFFFFull);
                int la = g - abase;
                float4 wb0 = sbox[la];
                p1 = pack2f(wb0.x, wb0.y);
                p2 = pack2f(wb0.z, wb0.w);
                p3 = pack2f(sarea[la], scls[la]);
            }
            unsigned dst = peer_mbox + (unsigned)((i & 1) * 32);
            asm volatile("st.shared::cluster.u64 [%0], %1;" :: "r"(dst),      "l"(k2) : "memory");
            asm volatile("st.shared::cluster.u64 [%0], %1;" :: "r"(dst + 8),  "l"(p1) : "memory");
            asm volatile("st.shared::cluster.u64 [%0], %1;" :: "r"(dst + 16), "l"(p2) : "memory");
            asm volatile("st.shared::cluster.u64 [%0], %1;" :: "r"(dst + 24), "l"(p3) : "memory");
        }
        asm volatile("barrier.cluster.arrive.aligned;" ::: "memory");
        asm volatile("barrier.cluster.wait.aligned;"   ::: "memory");

        unsigned long long pk = mbox[(i & 1) * 4 + 0];
        unsigned long long gk = (pk > k2) ? pk : k2;

        unsigned gk_hi = (unsigned)(gk >> 32);
        if (gk_hi <= 0x80000000u) {              // no positive score anywhere
            if (rank == 0) {
                for (int t = i * 4 + tid; t < MAXDET * 4; t += NT) boxes_out[t] = 0.f;
                for (int t = i + tid; t < MAXDET; t += NT) { cls_out[t] = 0.f; sco_out[t] = 0.f; }
                if (tid == 0) *nd_out = (float)i;
            }
            return;
        }

        // resolve global winner's box
        bool mine = (gk == k2);
        int  g    = 0x00FFFFFF - (int)(unsigned)(gk & 0xFFFFFFFFull);
        float4 wb; float wa;
        int la = g - abase;
        if (mine) {
            wb = sbox[la];
            wa = sarea[la];
            if (tid == 0) {
                boxes_out[i * 4 + 0] = wb.x;
                boxes_out[i * 4 + 1] = wb.y;
                boxes_out[i * 4 + 2] = wb.z;
                boxes_out[i * 4 + 3] = wb.w;
                cls_out[i] = scls[la];
                sco_out[i] = unmapf(gk_hi);
            }
        } else {
            unsigned long long p1 = mbox[(i & 1) * 4 + 1];
            unsigned long long p2 = mbox[(i & 1) * 4 + 2];
            unsigned long long p3 = mbox[(i & 1) * 4 + 3];
            wb.x = __uint_as_float((unsigned)(p1 & 0xFFFFFFFFull));
            wb.y = __uint_as_float((unsigned)(p1 >> 32));
            wb.z = __uint_as_float((unsigned)(p2 & 0xFFFFFFFFull));
            wb.w = __uint_as_float((unsigned)(p2 >> 32));
            wa   = __uint_as_float((unsigned)(p3 & 0xFFFFFFFFull));
        }

        // suppression over my half: sparse bitmask walk, guard-banded IoU test
        unsigned cleared = 0;
        unsigned m = mask;
        while (m) {
            int s = __ffs(m) - 1;
            m &= m - 1;
            int a = (s << NT_LOG2) + tid;
            float4 bb = sbox[a];
            float yy1 = fmaxf(wb.x, bb.x);
            float xx1 = fmaxf(wb.y, bb.y);
            float yy2 = fminf(wb.z, bb.z);
            float xx2 = fminf(wb.w, bb.w);
            float dy = fmaxf(__fsub_rn(yy2, yy1), 0.f);
            float dx = fmaxf(__fsub_rn(xx2, xx1), 0.f);
            float inter = __fmul_rn(dy, dx);
            float uni = __fsub_rn(__fadd_rn(wa, sarea[a]), inter);
            float t   = __fmaf_rn(-IOU_T, uni, inter);
            float bnd = 3e-7f * uni;
            bool sup;
            if (t > bnd)       sup = true;
            else if (t < -bnd) sup = false;
            else               sup = (uni > 0.f) && (__fdiv_rn(inter, uni) > IOU_T);
            if (sup) cleared |= (1u << s);
        }
        // winner slot always dies in its owning CTA (degenerate zero-area case)
        if (mine && (la & (NT - 1)) == tid) cleared |= 1u << (la >> NT_LOG2);

        if (cleared) {
            mask &= ~cleared;
            if (local) {
                unsigned lg = 0x00FFFFFFu - (unsigned)(local & 0xFFFFFFFFull);
                int bs = ((int)lg - abase) >> NT_LOG2;
                if (cleared & (1u << bs)) {      // cached best died -> rescan (regs only)
                    local = 0ull;
                    #pragma unroll
                    for (int s = 0; s < PERH; s++) {
                        if (mask & (1u << s)) {
                            unsigned long long kk =
                                ((unsigned long long)msc[s] << 32) |
                                (unsigned)(0x00FFFFFF - (abase + s * NT + tid));
                            if (kk > local) local = kk;
                        }
                    }
                }
            }
        }
    }
    if (rank == 0 && tid == 0) *nd_out = (float)MAXDET;
}

extern "C" void kernel_launch(void* const* d_in, const int* in_sizes, int n_in,
                              void* d_out, int out_size)
{
    (void)in_sizes; (void)n_in; (void)out_size;
    const float* in = (const float*)d_in[0];
    float* out = (float*)d_out;
    cudaFuncSetAttribute(yolo_nms_kernel,
                         cudaFuncAttributeMaxDynamicSharedMemorySize, SMEM_BYTES);
    yolo_nms_kernel<<<BATCH * CLU, NT, SMEM_BYTES>>>(in, out);
}

// round 6
// speedup vs baseline: 4.2396x; 1.8746x over previous
#include <cuda_runtime.h>

#define NIMG    64
#define CH      36
#define NCLS    32
#define ANCH    8400
#define NT      512
#define MAXDET  100
#define CONF_T  0.25f
#define IOU_T   0.45f
#define WCAP    2048          // candidate window capacity
#define SLOTS   4             // sorted candidates per thread (NT*SLOTS = WCAP)
#define HB      8192          // histogram bins

// ---------------- global scratch (static __device__: allowed) ----------------
__device__ unsigned long long g_key[NIMG][ANCH];
__device__ float4             g_box[NIMG][ANCH];
__device__ float              g_area[NIMG][ANCH];
__device__ float              g_cls[NIMG][ANCH];

static __device__ __forceinline__ unsigned mapf(float f) {
    unsigned u = __float_as_uint(f);
    return (u & 0x80000000u) ? ~u : (u | 0x80000000u);
}
static __device__ __forceinline__ float unmapf(unsigned u) {
    return __uint_as_float((u & 0x80000000u) ? (u ^ 0x80000000u) : ~u);
}
// monotone score bin: mapped scores for best in [CONF,1.0) span
// [0xBE800000, 0xBF800000) = 2^24 codes -> 8192 uniform bins of 2^11 codes.
static __device__ __forceinline__ int keybin(unsigned long long k) {
    unsigned hi = (unsigned)(k >> 32);
    unsigned d  = hi - 0xBE800000u;       // mapf(0.25f)
    int bn = (int)(d >> 11);
    return bn > (HB - 1) ? (HB - 1) : bn;
}

// exact-decision IoU > IOU_T test (guard-banded FMA, __fdiv_rn only in band)
static __device__ __forceinline__ bool sup_test(float4 w, float wa, float4 b, float ba) {
    float yy1 = fmaxf(w.x, b.x), xx1 = fmaxf(w.y, b.y);
    float yy2 = fminf(w.z, b.z), xx2 = fminf(w.w, b.w);
    float dy = fmaxf(__fsub_rn(yy2, yy1), 0.f);
    float dx = fmaxf(__fsub_rn(xx2, xx1), 0.f);
    float inter = __fmul_rn(dy, dx);
    float uni = __fsub_rn(__fadd_rn(wa, ba), inter);
    float t   = __fmaf_rn(-IOU_T, uni, inter);
    float bnd = 3e-7f * uni;
    if (t > bnd)  return true;
    if (t < -bnd) return false;
    return (uni > 0.f) && (__fdiv_rn(inter, uni) > IOU_T);
}

// ---------------- kernel 1: decode (bandwidth-bound, 256 CTAs) ----------------
__global__ __launch_bounds__(NT)
void decode_kernel(const float* __restrict__ in)
{
    const int img = blockIdx.y;
    const int chk = blockIdx.x;          // 4 chunks of 2100 anchors
    const float* base = in + (size_t)img * CH * ANCH;
    const int lo = chk * 2100;

    for (int a = lo + threadIdx.x; a < lo + 2100; a += NT) {
        float xc = base[a];
        float yc = base[ANCH + a];
        float w  = base[2 * ANCH + a];
        float h  = base[3 * ANCH + a];
        float best = base[4 * ANCH + a];
        int bc = 0;
        #pragma unroll
        for (int c = 1; c < NCLS; c++) {
            float v = base[(4 + c) * ANCH + a];
            if (v > best) { best = v; bc = c; }   // first-max == jnp.argmax
        }
        float y1 = fminf(fmaxf(yc - 0.5f * h, 0.f), 1.f);
        float x1 = fminf(fmaxf(xc - 0.5f * w, 0.f), 1.f);
        float y2 = fminf(fmaxf(yc + 0.5f * h, 0.f), 1.f);
        float x2 = fminf(fmaxf(xc + 0.5f * w, 0.f), 1.f);
        float area = __fmul_rn(__fsub_rn(y2, y1), __fsub_rn(x2, x1));
        unsigned long long key = 0ull;
        if (best >= CONF_T)
            key = ((unsigned long long)mapf(best) << 32) | (unsigned)(0xFFFFFF - a);
        g_key[img][a]  = key;
        g_box[img][a]  = make_float4(y1, x1, y2, x2);
        g_area[img][a] = area;
        g_cls[img][a]  = (float)bc;
    }
}

// ---------------- kernel 2: sorted-scan NMS (1 CTA / image) ----------------
// SMEM layout (bytes)
#define OFF_SKEY   0                       // u64[8400]   = 67200
#define OFF_HIST   67200                   // u32[8192]   = 32768
#define OFF_SA     99968                   // u32[512]
#define OFF_SB     102016                  // u32[512]
#define OFF_CKEY   104064                  // u64[2048]   = 16384
#define OFF_CBOX   120448                  // float4[2048]= 32768
#define OFF_CAREA  153216                  // f32[2048]
#define OFF_CCLS   161408                  // f32[2048]
#define OFF_ACCB   169600                  // float4[100] -> 1600
#define OFF_ACCA   171200                  // f32[100] -> 400
#define OFF_BAL    171600                  // u32[2][48] = 384
#define OFF_MISC   171984                  // u32[12]
#define SMEM_TOTAL 172032

__global__ __launch_bounds__(NT, 1)
void nms_kernel(float* __restrict__ out)
{
    extern __shared__ char smem[];
    unsigned long long* skey  = (unsigned long long*)(smem + OFF_SKEY);
    unsigned*           hist  = (unsigned*)(smem + OFF_HIST);
    unsigned*           sA    = (unsigned*)(smem + OFF_SA);
    unsigned*           sB    = (unsigned*)(smem + OFF_SB);
    unsigned long long* ckey  = (unsigned long long*)(smem + OFF_CKEY);
    float4*             cbox  = (float4*)(smem + OFF_CBOX);
    float*              carea = (float*)(smem + OFF_CAREA);
    float*              ccls  = (float*)(smem + OFF_CCLS);
    float4*             accb  = (float4*)(smem + OFF_ACCB);
    float*              acca  = (float*)(smem + OFF_ACCA);
    unsigned*           bal   = (unsigned*)(smem + OFF_BAL);
    unsigned*           misc  = (unsigned*)(smem + OFF_MISC);

    const int tid  = threadIdx.x;
    const int img  = blockIdx.x;
    const int wid  = tid >> 5;
    const int lane = tid & 31;

    float* boxes_out = out + (size_t)img * MAXDET * 4;
    float* cls_out   = out + (size_t)NIMG * MAXDET * 4 + (size_t)img * MAXDET;
    float* sco_out   = out + (size_t)NIMG * MAXDET * 5 + (size_t)img * MAXDET;
    float* nd_out    = out + (size_t)NIMG * MAXDET * 6 + img;

    // --- load keys to smem + histogram ---
    for (int i = tid; i < HB; i += NT) hist[i] = 0;
    __syncthreads();
    for (int it = 0; it < 17; it++) {
        int i = tid + it * NT;
        if (i < ANCH) {
            unsigned long long k = g_key[img][i];
            skey[i] = k;
            if (k) atomicAdd(&hist[keybin(k)], 1u);
        }
    }
    __syncthreads();

    // --- chunk sums + inclusive suffix scan over 512 chunks ---
    {
        unsigned s = 0;
        #pragma unroll
        for (int b = 0; b < 16; b++) s += hist[tid * 16 + b];
        sA[tid] = s;
    }
    __syncthreads();
    {
        unsigned* src = sA; unsigned* dst = sB;
        for (int off = 1; off < NT; off <<= 1) {
            unsigned v = src[tid] + ((tid + off < NT) ? src[tid + off] : 0u);
            __syncthreads();
            dst[tid] = v;
            __syncthreads();
            unsigned* t2 = src; src = dst; dst = t2;
        }
        if (src != sA) { sA[tid] = src[tid]; __syncthreads(); }
    }
    const unsigned totalPos = sA[0];   // sA[c] = count of keys in bins >= c*16

    int na = 0;
    unsigned cumHi = 0;     // cumAbove(hi)
    int hi = HB;            // current window upper bin bound (exclusive)
    int it2 = 0;

    while (na < MAXDET && cumHi < totalPos) {
        // --- find lo: min bin with cumAbove(bin)-cumHi <= WCAP ---
        if (tid == 0) { misc[0] = 0; misc[1] = 0xFFFFFFFFu; misc[2] = 0; }
        __syncthreads();
        int mylo = -1; unsigned myloCum = 0;
        {
            unsigned carry = (tid < NT - 1) ? sA[tid + 1] : 0u;
            for (int b = tid * 16 + 15; b >= tid * 16; b--) {
                carry += hist[b];
                if (b < hi && (carry - cumHi) <= WCAP) { mylo = b; myloCum = carry; }
            }
        }
        if (mylo >= 0) atomicMin(&misc[1], (unsigned)mylo);
        __syncthreads();
        int lo = (int)misc[1];
        if (lo == (int)0xFFFFFFFF) {            // pathological fat bin: clamp
            lo = hi - 1;
            if (tid == 0) misc[2] = cumHi + hist[lo];
        } else if (mylo == lo) {
            misc[2] = myloCum;
        }
        __syncthreads();
        unsigned loCum = misc[2];

        // --- select window [lo, hi) into ckey (unordered) ---
        for (int i = tid; i < WCAP; i += NT) ckey[i] = 0ull;
        __syncthreads();
        for (int it = 0; it < 17; it++) {
            int i = tid + it * NT;
            unsigned long long k = (i < ANCH) ? skey[i] : 0ull;
            bool cond = false;
            if (k) { int bn = keybin(k); cond = (bn >= lo && bn < hi); }
            unsigned act = __ballot_sync(0xFFFFFFFFu, cond);
            unsigned basep = 0;
            int leader = act ? (__ffs(act) - 1) : 0;
            if (act && lane == leader) basep = atomicAdd(&misc[0], __popc(act));
            basep = __shfl_sync(0xFFFFFFFFu, basep, leader);
            if (cond) {
                unsigned pos = basep + __popc(act & ((1u << lane) - 1));
                if (pos < WCAP) ckey[pos] = k;
            }
        }
        __syncthreads();
        int selCount = (int)misc[0]; if (selCount > WCAP) selCount = WCAP;

        if (selCount > 0) {
            // --- bitonic sort ckey[0..2048) descending ---
            for (int k = 2; k <= WCAP; k <<= 1) {
                for (int j = k >> 1; j > 0; j >>= 1) {
                    for (int i = tid; i < WCAP; i += NT) {
                        int ixj = i ^ j;
                        if (ixj > i) {
                            unsigned long long a = ckey[i], b2 = ckey[ixj];
                            bool down = ((i & k) == 0);
                            if (down ? (a < b2) : (a > b2)) { ckey[i] = b2; ckey[ixj] = a; }
                        }
                    }
                    __syncthreads();
                }
            }

            // --- gather my SLOTS candidates (regs + smem) ---
            float4 rb[SLOTS]; float ra[SLOTS];
            unsigned am = 0;
            #pragma unroll
            for (int s = 0; s < SLOTS; s++) {
                int j = tid * SLOTS + s;
                if (j < selCount) {
                    unsigned long long k = ckey[j];
                    int idx = 0xFFFFFF - (int)(unsigned)(k & 0xFFFFFFu);
                    float4 bx = g_box[img][idx];
                    float  aa = g_area[img][idx];
                    rb[s] = bx; ra[s] = aa;
                    cbox[j] = bx; carea[j] = aa; ccls[j] = g_cls[img][idx];
                    am |= (1u << s);
                } else { rb[s] = make_float4(0,0,0,0); ra[s] = 0.f; }
            }

            // --- pre-test vs already-accepted boxes (refill windows) ---
            for (int a2 = 0; a2 < na; a2++) {
                float4 ab = accb[a2]; float aa = acca[a2];
                #pragma unroll
                for (int s = 0; s < SLOTS; s++)
                    if ((am >> s) & 1)
                        if (sup_test(ab, aa, rb[s], ra[s])) am &= ~(1u << s);
            }
            __syncthreads();   // cbox/carea/ccls visible to all before accept loop

            // --- accept scan: first-alive-in-order == next greedy winner ---
            while (na < MAXDET) {
                int p = (it2 & 1) * 48; it2++;
                unsigned anyw = __ballot_sync(0xFFFFFFFFu, am != 0);
                int sf = am ? (__ffs(am) - 1) : 0;
                unsigned b0 = __ballot_sync(0xFFFFFFFFu, am && (sf & 1));
                unsigned b1 = __ballot_sync(0xFFFFFFFFu, am && (sf & 2));
                if (lane == 0) { bal[p + wid] = anyw; bal[p + 16 + wid] = b0; bal[p + 32 + wid] = b1; }
                __syncthreads();
                unsigned v = (lane < 16) ? bal[p + lane] : 0u;
                unsigned ww = __ballot_sync(0xFFFFFFFFu, v != 0);
                if (ww == 0) break;                       // window exhausted
                int wf = __ffs(ww) - 1;
                unsigned aw = bal[p + wf];
                int lt = __ffs(aw) - 1;
                int tstar = wf * 32 + lt;
                int sstar = (int)(((bal[p + 16 + wf] >> lt) & 1) | (((bal[p + 32 + wf] >> lt) & 1) << 1));
                int jstar = tstar * SLOTS + sstar;

                float4 wbx = cbox[jstar];                 // broadcast LDS
                float  wav = carea[jstar];

                if (tid == 0) {
                    boxes_out[na * 4 + 0] = wbx.x;
                    boxes_out[na * 4 + 1] = wbx.y;
                    boxes_out[na * 4 + 2] = wbx.z;
                    boxes_out[na * 4 + 3] = wbx.w;
                    cls_out[na] = ccls[jstar];
                    sco_out[na] = unmapf((unsigned)(ckey[jstar] >> 32));
                    accb[na] = wbx; acca[na] = wav;
                }
                if (tid == tstar) am &= ~(1u << sstar);   // winner consumed
                #pragma unroll
                for (int s = 0; s < SLOTS; s++)
                    if ((am >> s) & 1)
                        if (sup_test(wbx, wav, rb[s], ra[s])) am &= ~(1u << s);
                na++;
            }
            __syncthreads();   // protect ckey/cbox reuse by next window
        }
        hi = lo;
        cumHi = loCum;
    }

    // --- pad remaining outputs with zeros; write num_det ---
    for (int t = na * 4 + tid; t < MAXDET * 4; t += NT) boxes_out[t] = 0.f;
    for (int t = na + tid; t < MAXDET; t += NT) { cls_out[t] = 0.f; sco_out[t] = 0.f; }
    if (tid == 0) *nd_out = (float)na;
}

extern "C" void kernel_launch(void* const* d_in, const int* in_sizes, int n_in,
                              void* d_out, int out_size)
{
    (void)in_sizes; (void)n_in; (void)out_size;
    const float* in = (const float*)d_in[0];
    float* out = (float*)d_out;
    cudaFuncSetAttribute(nms_kernel,
                         cudaFuncAttributeMaxDynamicSharedMemorySize, SMEM_TOTAL);
    decode_kernel<<<dim3(4, NIMG), NT>>>(in);
    nms_kernel<<<NIMG, NT, SMEM_TOTAL>>>(out);
}

// round 7
// speedup vs baseline: 5.4955x; 1.2962x over previous
#include <cuda_runtime.h>

#define NIMG    64
#define CH      36
#define NCLS    32
#define ANCH    8400
#define NT      512
#define MAXDET  100
#define CONF_T  0.25f
#define IOU_T   0.45f
#define WCAP    512           // candidate window capacity (1 per thread)
#define HB      8192          // histogram bins

// ---------------- global scratch (static __device__: allowed) ----------------
__device__ unsigned long long g_key[NIMG][ANCH];
__device__ float4             g_box[NIMG][ANCH];
__device__ float              g_area[NIMG][ANCH];
__device__ float              g_cls[NIMG][ANCH];

static __device__ __forceinline__ unsigned mapf(float f) {
    unsigned u = __float_as_uint(f);
    return (u & 0x80000000u) ? ~u : (u | 0x80000000u);
}
static __device__ __forceinline__ float unmapf(unsigned u) {
    return __uint_as_float((u & 0x80000000u) ? (u ^ 0x80000000u) : ~u);
}
// monotone score bin: mapped scores for best in [CONF,1.0) span
// [0xBE800000, 0xBF800000) = 2^24 codes -> 8192 uniform bins of 2^11 codes.
static __device__ __forceinline__ int keybin(unsigned long long k) {
    unsigned hi = (unsigned)(k >> 32);
    unsigned d  = hi - 0xBE800000u;       // mapf(0.25f)
    int bn = (int)(d >> 11);
    return bn > (HB - 1) ? (HB - 1) : bn;
}

// exact-decision IoU > IOU_T test (guard-banded FMA, __fdiv_rn only in band)
static __device__ __forceinline__ bool sup_test(float4 w, float wa, float4 b, float ba) {
    float yy1 = fmaxf(w.x, b.x), xx1 = fmaxf(w.y, b.y);
    float yy2 = fminf(w.z, b.z), xx2 = fminf(w.w, b.w);
    float dy = fmaxf(__fsub_rn(yy2, yy1), 0.f);
    float dx = fmaxf(__fsub_rn(xx2, xx1), 0.f);
    float inter = __fmul_rn(dy, dx);
    float uni = __fsub_rn(__fadd_rn(wa, ba), inter);
    float t   = __fmaf_rn(-IOU_T, uni, inter);
    float bnd = 3e-7f * uni;
    if (t > bnd)  return true;
    if (t < -bnd) return false;
    return (uni > 0.f) && (__fdiv_rn(inter, uni) > IOU_T);
}

// ---------------- kernel 1: decode (bandwidth-bound, 256 CTAs) ----------------
__global__ __launch_bounds__(NT)
void decode_kernel(const float* __restrict__ in)
{
    const int img = blockIdx.y;
    const int chk = blockIdx.x;          // 4 chunks of 2100 anchors
    const float* base = in + (size_t)img * CH * ANCH;
    const int lo = chk * 2100;

    for (int a = lo + threadIdx.x; a < lo + 2100; a += NT) {
        float xc = base[a];
        float yc = base[ANCH + a];
        float w  = base[2 * ANCH + a];
        float h  = base[3 * ANCH + a];
        float best = base[4 * ANCH + a];
        int bc = 0;
        #pragma unroll
        for (int c = 1; c < NCLS; c++) {
            float v = base[(4 + c) * ANCH + a];
            if (v > best) { best = v; bc = c; }   // first-max == jnp.argmax
        }
        float y1 = fminf(fmaxf(yc - 0.5f * h, 0.f), 1.f);
        float x1 = fminf(fmaxf(xc - 0.5f * w, 0.f), 1.f);
        float y2 = fminf(fmaxf(yc + 0.5f * h, 0.f), 1.f);
        float x2 = fminf(fmaxf(xc + 0.5f * w, 0.f), 1.f);
        float area = __fmul_rn(__fsub_rn(y2, y1), __fsub_rn(x2, x1));
        unsigned long long key = 0ull;
        if (best >= CONF_T)
            key = ((unsigned long long)mapf(best) << 32) | (unsigned)(0xFFFFFF - a);
        g_key[img][a]  = key;
        g_box[img][a]  = make_float4(y1, x1, y2, x2);
        g_area[img][a] = area;
        g_cls[img][a]  = (float)bc;
    }
}

// ---------------- kernel 2: sorted-scan NMS (1 CTA / image) ----------------
// SMEM layout (bytes)
#define OFF_SKEY   0                       // u64[8400]  = 67200
#define OFF_HIST   67200                   // u32[8192]  = 32768
#define OFF_SA     99968                   // u32[512]
#define OFF_SB     102016                  // u32[512]
#define OFF_CKEY   104064                  // u64[512]   = 4096
#define OFF_CBOX   108160                  // float4[512]= 8192
#define OFF_CAREA  116352                  // f32[512]
#define OFF_CCLS   118400                  // f32[512]
#define OFF_ACCB   120448                  // float4[100]= 1600
#define OFF_ACCA   122048                  // f32[100]   = 400
#define OFF_MISC   122448                  // u32[12]
#define SMEM_TOTAL 122496

__global__ __launch_bounds__(NT, 1)
void nms_kernel(float* __restrict__ out)
{
    extern __shared__ char smem[];
    unsigned long long* skey  = (unsigned long long*)(smem + OFF_SKEY);
    unsigned*           hist  = (unsigned*)(smem + OFF_HIST);
    unsigned*           sA    = (unsigned*)(smem + OFF_SA);
    unsigned*           sB    = (unsigned*)(smem + OFF_SB);
    unsigned long long* ckey  = (unsigned long long*)(smem + OFF_CKEY);
    float4*             cbox  = (float4*)(smem + OFF_CBOX);
    float*              carea = (float*)(smem + OFF_CAREA);
    float*              ccls  = (float*)(smem + OFF_CCLS);
    float4*             accb  = (float4*)(smem + OFF_ACCB);
    float*              acca  = (float*)(smem + OFF_ACCA);
    unsigned*           misc  = (unsigned*)(smem + OFF_MISC);

    const int tid  = threadIdx.x;
    const int img  = blockIdx.x;
    const int wid  = tid >> 5;
    const int lane = tid & 31;

    float* boxes_out = out + (size_t)img * MAXDET * 4;
    float* cls_out   = out + (size_t)NIMG * MAXDET * 4 + (size_t)img * MAXDET;
    float* sco_out   = out + (size_t)NIMG * MAXDET * 5 + (size_t)img * MAXDET;
    float* nd_out    = out + (size_t)NIMG * MAXDET * 6 + img;

    // --- load keys to smem + histogram ---
    for (int i = tid; i < HB; i += NT) hist[i] = 0;
    if (tid == 0) misc[3] = 0;   // accepted count
    __syncthreads();
    for (int it = 0; it < 17; it++) {
        int i = tid + it * NT;
        if (i < ANCH) {
            unsigned long long k = g_key[img][i];
            skey[i] = k;
            if (k) atomicAdd(&hist[keybin(k)], 1u);
        }
    }
    __syncthreads();

    // --- chunk sums + inclusive suffix scan over 512 chunks ---
    {
        unsigned s = 0;
        #pragma unroll
        for (int b = 0; b < 16; b++) s += hist[tid * 16 + b];
        sA[tid] = s;
    }
    __syncthreads();
    {
        unsigned* src = sA; unsigned* dst = sB;
        for (int off = 1; off < NT; off <<= 1) {
            unsigned v = src[tid] + ((tid + off < NT) ? src[tid + off] : 0u);
            __syncthreads();
            dst[tid] = v;
            __syncthreads();
            unsigned* t2 = src; src = dst; dst = t2;
        }
        if (src != sA) { sA[tid] = src[tid]; __syncthreads(); }
    }
    const unsigned totalPos = sA[0];

    int na = 0;
    unsigned cumHi = 0;
    int hi = HB;

    while (na < MAXDET && cumHi < totalPos) {
        // --- find lo: min bin with cumAbove(bin)-cumHi <= WCAP ---
        if (tid == 0) { misc[0] = 0; misc[1] = 0xFFFFFFFFu; misc[2] = 0; }
        __syncthreads();
        int mylo = -1; unsigned myloCum = 0;
        {
            unsigned carry = (tid < NT - 1) ? sA[tid + 1] : 0u;
            for (int b = tid * 16 + 15; b >= tid * 16; b--) {
                carry += hist[b];
                if (b < hi && (carry - cumHi) <= WCAP) { mylo = b; myloCum = carry; }
            }
        }
        if (mylo >= 0) atomicMin(&misc[1], (unsigned)mylo);
        __syncthreads();
        int lo = (int)misc[1];
        if (lo == (int)0xFFFFFFFF) {            // pathological fat bin: clamp
            lo = hi - 1;
            if (tid == 0) misc[2] = cumHi + hist[lo];
        } else if (mylo == lo) {
            misc[2] = myloCum;
        }
        __syncthreads();
        unsigned loCum = misc[2];

        // --- select window [lo, hi) into ckey (unordered) ---
        unsigned long long myk = 0ull;
        // zero via register default; positions beyond selCount handled below
        for (int it = 0; it < 17; it++) {
            int i = tid + it * NT;
            unsigned long long k = (i < ANCH) ? skey[i] : 0ull;
            bool cond = false;
            if (k) { int bn = keybin(k); cond = (bn >= lo && bn < hi); }
            unsigned act = __ballot_sync(0xFFFFFFFFu, cond);
            unsigned basep = 0;
            int leader = act ? (__ffs(act) - 1) : 0;
            if (act && lane == leader) basep = atomicAdd(&misc[0], __popc(act));
            basep = __shfl_sync(0xFFFFFFFFu, basep, leader);
            if (cond) {
                unsigned pos = basep + __popc(act & ((1u << lane) - 1));
                if (pos < WCAP) ckey[pos] = k;
            }
        }
        __syncthreads();
        int selCount = (int)misc[0]; if (selCount > WCAP) selCount = WCAP;

        if (selCount > 0) {
            // --- bitonic sort, 1 key/thread, descending; shuffles for j<32 ---
            unsigned long long v = (tid < selCount) ? ckey[tid] : 0ull;
            __syncthreads();   // ckey reused as exchange buffer
            #pragma unroll
            for (int k = 2; k <= NT; k <<= 1) {
                for (int j = k >> 1; j > 0; j >>= 1) {
                    unsigned long long o;
                    if (j >= 32) {
                        ckey[tid] = v;
                        __syncthreads();
                        o = ckey[tid ^ j];
                        __syncthreads();
                    } else {
                        o = __shfl_xor_sync(0xFFFFFFFFu, v, j);
                    }
                    bool dirDesc = ((tid & k) == 0);
                    bool lower   = ((tid & j) == 0);
                    bool takeMax = (dirDesc == lower);
                    v = takeMax ? (v > o ? v : o) : (v < o ? v : o);
                }
            }
            ckey[tid] = v;
            // gather boxes for my sorted candidate
            if (tid < selCount) {
                int idx = 0xFFFFFF - (int)(unsigned)(v & 0xFFFFFFu);
                cbox[tid]  = g_box[img][idx];
                carea[tid] = g_area[img][idx];
                ccls[tid]  = g_cls[img][idx];
            }
            __syncthreads();

            // --- warp 0: serial accept scan over sorted candidates ---
            if (wid == 0) {
                int lna = na;
                int pos = 0;
                while (lna < MAXDET && pos < selCount) {
                    int j = pos + lane;
                    float4 cb = make_float4(0.f, 0.f, 0.f, 0.f);
                    float ca = 0.f;
                    unsigned long long ck = 0ull;
                    bool alivec = false;
                    if (j < selCount) {
                        ck = ckey[j];
                        cb = cbox[j];
                        ca = carea[j];
                        alivec = true;
                    }
                    // pre-test vs all accepted so far (broadcast LDS)
                    for (int a2 = 0; a2 < lna && alivec; a2++)
                        if (sup_test(accb[a2], acca[a2], cb, ca)) alivec = false;

                    unsigned alive = __ballot_sync(0xFFFFFFFFu, alivec);
                    while (alive && lna < MAXDET) {
                        int l = __ffs(alive) - 1;
                        float wx = __shfl_sync(0xFFFFFFFFu, cb.x, l);
                        float wy = __shfl_sync(0xFFFFFFFFu, cb.y, l);
                        float wz = __shfl_sync(0xFFFFFFFFu, cb.z, l);
                        float wq = __shfl_sync(0xFFFFFFFFu, cb.w, l);
                        float wa = __shfl_sync(0xFFFFFFFFu, ca, l);
                        if (lane == l) {
                            boxes_out[lna * 4 + 0] = cb.x;
                            boxes_out[lna * 4 + 1] = cb.y;
                            boxes_out[lna * 4 + 2] = cb.z;
                            boxes_out[lna * 4 + 3] = cb.w;
                            cls_out[lna] = ccls[j];
                            sco_out[lna] = unmapf((unsigned)(ck >> 32));
                            accb[lna] = cb;
                            acca[lna] = ca;
                        }
                        float4 wb = make_float4(wx, wy, wz, wq);
                        if (lane > l) {
                            if (alivec && sup_test(wb, wa, cb, ca)) alivec = false;
                        } else {
                            alivec = false;   // consumed / already dead
                        }
                        lna++;
                        __syncwarp();         // accb[lna-1] visible to all lanes
                        alive = __ballot_sync(0xFFFFFFFFu, alivec);
                    }
                    pos += 32;
                    __syncwarp();
                }
                if (lane == 0) misc[3] = (unsigned)lna;
            }
            __syncthreads();
            na = (int)misc[3];
        }
        hi = lo;
        cumHi = loCum;
    }

    // --- pad remaining outputs with zeros; write num_det ---
    for (int t = na * 4 + tid; t < MAXDET * 4; t += NT) boxes_out[t] = 0.f;
    for (int t = na + tid; t < MAXDET; t += NT) { cls_out[t] = 0.f; sco_out[t] = 0.f; }
    if (tid == 0) *nd_out = (float)na;
}

extern "C" void kernel_launch(void* const* d_in, const int* in_sizes, int n_in,
                              void* d_out, int out_size)
{
    (void)in_sizes; (void)n_in; (void)out_size;
    const float* in = (const float*)d_in[0];
    float* out = (float*)d_out;
    cudaFuncSetAttribute(nms_kernel,
                         cudaFuncAttributeMaxDynamicSharedMemorySize, SMEM_TOTAL);
    decode_kernel<<<dim3(4, NIMG), NT>>>(in);
    nms_kernel<<<NIMG, NT, SMEM_TOTAL>>>(out);
}